// round 1
// baseline (speedup 1.0000x reference)
#include <cuda_runtime.h>
#include <cuda_bf16.h>
#include <cstdint>

// Problem constants (fixed shapes for this problem)
#define B_SZ 8192
#define I_SZ 256
#define O_SZ 256
#define C_SZ 32

#define TM 128
#define TN 128
#define TK 16

// Scratch (device globals — allocation-free per harness rules)
__device__ int   g_perm[B_SZ];
__device__ int   g_count[C_SZ];
__device__ int   g_offset[C_SZ];
__device__ float g_wt[C_SZ * O_SZ * I_SZ];   // [c][o][i], 8 MB

// ---------------------------------------------------------------------------
// Kernel 1: detect idx dtype (int32 vs int64), histogram, prefix, scatter perm
// Single block, 1024 threads.
// ---------------------------------------------------------------------------
__global__ void prep_kernel(const void* __restrict__ idx_ptr) {
    __shared__ int s_cnt[C_SZ];
    __shared__ int s_off[C_SZ];
    __shared__ int s_is64;

    const int tid = threadIdx.x;

    if (tid == 0) s_is64 = 1;
    if (tid < C_SZ) s_cnt[tid] = 0;
    __syncthreads();

    // Safe detection: only read the first B_SZ int32 words (valid for both
    // int32[B] and int64[B] buffers). int64 layout => odd words all zero and
    // even words in [0, 32).
    {
        const int* w = (const int*)idx_ptr;
        int ok = 1;
        for (int i = tid; i < B_SZ / 2; i += blockDim.x) {
            if (w[2 * i + 1] != 0) ok = 0;
            if ((unsigned)w[2 * i] >= 32u) ok = 0;
        }
        if (!ok) atomicAnd(&s_is64, 0);
    }
    __syncthreads();
    const int is64 = s_is64;

    // Histogram
    for (int i = tid; i < B_SZ; i += blockDim.x) {
        int c = is64 ? (int)((const long long*)idx_ptr)[i]
                     : ((const int*)idx_ptr)[i];
        atomicAdd(&s_cnt[c], 1);
    }
    __syncthreads();

    if (tid == 0) {
        int acc = 0;
        for (int c = 0; c < C_SZ; c++) {
            s_off[c]    = acc;
            g_offset[c] = acc;
            g_count[c]  = s_cnt[c];
            acc += s_cnt[c];
        }
    }
    __syncthreads();

    // Reuse s_cnt as scatter cursors
    if (tid < C_SZ) s_cnt[tid] = s_off[tid];
    __syncthreads();

    for (int i = tid; i < B_SZ; i += blockDim.x) {
        int c = is64 ? (int)((const long long*)idx_ptr)[i]
                     : ((const int*)idx_ptr)[i];
        int pos = atomicAdd(&s_cnt[c], 1);
        g_perm[pos] = i;
    }
}

// ---------------------------------------------------------------------------
// Kernel 2: transpose weight [O,I,C] -> g_wt [C,O,I]  (coalesced both sides)
// Grid: O_SZ blocks (one per o), 256 threads. Per-o slab is contiguous
// 8192 floats (linear over (i,c)); transpose via padded smem.
// ---------------------------------------------------------------------------
__global__ void transpose_kernel(const float* __restrict__ weight) {
    __shared__ float s[I_SZ * 33];  // pad: [i*33 + c] avoids bank conflicts
    const int o = blockIdx.x;
    const float* src = weight + (size_t)o * (I_SZ * C_SZ);

    for (int l = threadIdx.x; l < I_SZ * C_SZ; l += blockDim.x) {
        int i = l >> 5, c = l & 31;
        s[i * 33 + c] = src[l];
    }
    __syncthreads();

    for (int l = threadIdx.x; l < I_SZ * C_SZ; l += blockDim.x) {
        int c = l >> 8, i = l & 255;
        g_wt[(size_t)c * (O_SZ * I_SZ) + (size_t)o * I_SZ + i] = s[i * 33 + c];
    }
}

// ---------------------------------------------------------------------------
// Kernel 3: per-channel tiled GEMM with gathered rows.
// out[row, n] = sum_k x[row, k] * g_wt[c][n][k] + bias[n, c]
// Grid: (n_tiles=2, m_tiles_max=64, C=32). Blocks beyond channel count exit.
// 256 threads, 128x128 tile, TK=16, double-buffered smem, 8x8 micro-tile.
// ---------------------------------------------------------------------------
__global__ __launch_bounds__(256, 1)
void gemm_kernel(const float* __restrict__ x,
                 const float* __restrict__ bias,
                 float* __restrict__ out) {
    const int c   = blockIdx.z;
    const int cnt = g_count[c];
    const int m0  = blockIdx.y * TM;
    if (m0 >= cnt) return;
    const int rows = min(TM, cnt - m0);
    const int n0   = blockIdx.x * TN;
    const int base = g_offset[c] + m0;

    __shared__ int   s_row[TM];
    __shared__ float s_bias[TN];
    __shared__ float As[2][TK][TM];
    __shared__ float Bs[2][TK][TN];

    const int tid = threadIdx.x;

    if (tid < TM) s_row[tid] = g_perm[base + min(tid, rows - 1)];
    if (tid < TN) s_bias[tid] = bias[(size_t)(n0 + tid) * C_SZ + c];
    __syncthreads();

    const float* wc = g_wt + (size_t)c * (O_SZ * I_SZ);

    // Stage loaders: each thread loads 2 float4 for A and 2 for B.
    auto loadA = [&](int kb, int buf) {
#pragma unroll
        for (int it = 0; it < 2; it++) {
            int idx = tid + it * 256;
            int m = idx >> 2, q = idx & 3;
            float4 v = *(const float4*)(x + (size_t)s_row[m] * I_SZ + kb + q * 4);
            As[buf][q * 4 + 0][m] = v.x;
            As[buf][q * 4 + 1][m] = v.y;
            As[buf][q * 4 + 2][m] = v.z;
            As[buf][q * 4 + 3][m] = v.w;
        }
    };
    auto loadB = [&](int kb, int buf) {
#pragma unroll
        for (int it = 0; it < 2; it++) {
            int idx = tid + it * 256;
            int n = idx >> 2, q = idx & 3;
            float4 v = *(const float4*)(wc + (size_t)(n0 + n) * I_SZ + kb + q * 4);
            Bs[buf][q * 4 + 0][n] = v.x;
            Bs[buf][q * 4 + 1][n] = v.y;
            Bs[buf][q * 4 + 2][n] = v.z;
            Bs[buf][q * 4 + 3][n] = v.w;
        }
    };

    const int tx = tid & 15;   // n direction
    const int ty = tid >> 4;   // m direction

    float acc[8][8];
#pragma unroll
    for (int i = 0; i < 8; i++)
#pragma unroll
        for (int j = 0; j < 8; j++) acc[i][j] = 0.0f;

    loadA(0, 0);
    loadB(0, 0);
    __syncthreads();

#pragma unroll 1
    for (int kb = 0; kb < I_SZ; kb += TK) {
        int buf = (kb / TK) & 1;
        if (kb + TK < I_SZ) {
            loadA(kb + TK, buf ^ 1);
            loadB(kb + TK, buf ^ 1);
        }
#pragma unroll
        for (int k = 0; k < TK; k++) {
            float a[8], b[8];
            float4 a0 = *(const float4*)&As[buf][k][ty * 8 + 0];
            float4 a1 = *(const float4*)&As[buf][k][ty * 8 + 4];
            float4 b0 = *(const float4*)&Bs[buf][k][tx * 8 + 0];
            float4 b1 = *(const float4*)&Bs[buf][k][tx * 8 + 4];
            a[0]=a0.x; a[1]=a0.y; a[2]=a0.z; a[3]=a0.w;
            a[4]=a1.x; a[5]=a1.y; a[6]=a1.z; a[7]=a1.w;
            b[0]=b0.x; b[1]=b0.y; b[2]=b0.z; b[3]=b0.w;
            b[4]=b1.x; b[5]=b1.y; b[6]=b1.z; b[7]=b1.w;
#pragma unroll
            for (int i = 0; i < 8; i++)
#pragma unroll
                for (int j = 0; j < 8; j++)
                    acc[i][j] = fmaf(a[i], b[j], acc[i][j]);
        }
        __syncthreads();
    }

    // Epilogue: add bias, scatter rows back
#pragma unroll
    for (int i = 0; i < 8; i++) {
        int m = ty * 8 + i;
        if (m < rows) {
            int row = s_row[m];
            float* op = out + (size_t)row * O_SZ + n0 + tx * 8;
            float4 v0, v1;
            v0.x = acc[i][0] + s_bias[tx * 8 + 0];
            v0.y = acc[i][1] + s_bias[tx * 8 + 1];
            v0.z = acc[i][2] + s_bias[tx * 8 + 2];
            v0.w = acc[i][3] + s_bias[tx * 8 + 3];
            v1.x = acc[i][4] + s_bias[tx * 8 + 4];
            v1.y = acc[i][5] + s_bias[tx * 8 + 5];
            v1.z = acc[i][6] + s_bias[tx * 8 + 6];
            v1.w = acc[i][7] + s_bias[tx * 8 + 7];
            *(float4*)(op + 0) = v0;
            *(float4*)(op + 4) = v1;
        }
    }
}

// ---------------------------------------------------------------------------
// Launch
// Inputs (metadata order): x [B,I] f32, idx_channel [B] int64/int32,
//                          weight [O,I,C] f32, bias [O,C] f32
// Output: out [B,O] f32
// ---------------------------------------------------------------------------
extern "C" void kernel_launch(void* const* d_in, const int* in_sizes, int n_in,
                              void* d_out, int out_size) {
    const float* x      = (const float*)d_in[0];
    const void*  idx    = d_in[1];
    const float* weight = (const float*)d_in[2];
    const float* bias   = (const float*)d_in[3];
    float* out = (float*)d_out;

    prep_kernel<<<1, 1024>>>(idx);
    transpose_kernel<<<O_SZ, 256>>>(weight);
    // worst case: one channel holds all B samples -> 64 m-tiles
    dim3 grid(TN == 128 ? O_SZ / TN : 2, B_SZ / TM, C_SZ);
    gemm_kernel<<<grid, 256>>>(x, bias, out);
}

// round 3
// speedup vs baseline: 1.8463x; 1.8463x over previous
#include <cuda_runtime.h>
#include <cuda_fp16.h>
#include <cstdint>

#define B_SZ 8192
#define I_SZ 256
#define O_SZ 256
#define C_SZ 32
#define FULLMASK 0xFFFFFFFFu

// ---------------- scratch (device globals; allocation-free) ----------------
__device__ int g_perm[B_SZ];
__device__ int g_count[C_SZ];
__device__ int g_offset[C_SZ];
__device__ __half g_wq[C_SZ * O_SZ * I_SZ];  // [c][o][i] fp16, 4 MB

// ---------------------------------------------------------------------------
// prep: idx dtype detect + histogram + prefix + stable-ish scatter (warp-agg)
// ---------------------------------------------------------------------------
__global__ void prep_kernel(const void* __restrict__ idx_ptr) {
    __shared__ int s_cnt[C_SZ];
    __shared__ int s_off[C_SZ];
    __shared__ int s_is64;
    const int tid = threadIdx.x;
    const int lane = tid & 31;

    if (tid == 0) s_is64 = 1;
    if (tid < C_SZ) s_cnt[tid] = 0;
    __syncthreads();

    {
        const int4* w = (const int4*)idx_ptr;
        int ok = 1;
        for (int i = tid; i < B_SZ / 4; i += 1024) {
            int4 v = w[i];
            if (v.y | v.w) ok = 0;
            if ((unsigned)v.x >= 32u || (unsigned)v.z >= 32u) ok = 0;
        }
        if (!ok) atomicAnd(&s_is64, 0);
    }
    __syncthreads();
    const int is64 = s_is64;

    for (int i = tid; i < B_SZ; i += 1024) {
        int c = is64 ? (int)((const long long*)idx_ptr)[i]
                     : ((const int*)idx_ptr)[i];
        unsigned mask = __match_any_sync(FULLMASK, c);
        if (lane == (__ffs(mask) - 1)) atomicAdd(&s_cnt[c], __popc(mask));
    }
    __syncthreads();

    if (tid == 0) {
        int acc = 0;
        for (int c = 0; c < C_SZ; c++) {
            s_off[c] = acc;
            g_offset[c] = acc;
            g_count[c] = s_cnt[c];
            acc += s_cnt[c];
        }
    }
    __syncthreads();
    if (tid < C_SZ) s_cnt[tid] = s_off[tid];
    __syncthreads();

    for (int i = tid; i < B_SZ; i += 1024) {
        int c = is64 ? (int)((const long long*)idx_ptr)[i]
                     : ((const int*)idx_ptr)[i];
        unsigned mask = __match_any_sync(FULLMASK, c);
        int leader = __ffs(mask) - 1;
        int r = __popc(mask & ((1u << lane) - 1u));
        int base = 0;
        if (lane == leader) base = atomicAdd(&s_cnt[c], __popc(mask));
        base = __shfl_sync(FULLMASK, base, leader);
        g_perm[base + r] = i;
    }
}

// ---------------------------------------------------------------------------
// conv_w: weight [O][I][C] fp32 -> g_wq [C][O][I] fp16 (transpose + convert)
// ---------------------------------------------------------------------------
__global__ void conv_w_kernel(const float* __restrict__ weight) {
    __shared__ float s[I_SZ * 33];
    const int o = blockIdx.x;
    const float* src = weight + (size_t)o * (I_SZ * C_SZ);

    for (int l = threadIdx.x; l < I_SZ * C_SZ; l += blockDim.x) {
        int i = l >> 5, c = l & 31;
        s[i * 33 + c] = src[l];
    }
    __syncthreads();

    for (int u = threadIdx.x; u < (I_SZ * C_SZ) / 4; u += blockDim.x) {
        int c = u >> 6, i4 = u & 63;
        union { uint2 uu; __half h[4]; } H;
#pragma unroll
        for (int j = 0; j < 4; j++)
            H.h[j] = __float2half_rn(s[(i4 * 4 + j) * 33 + c]);
        size_t off = ((size_t)c << 16) + ((size_t)o << 8) + (size_t)i4 * 4;
        *(uint2*)(g_wq + off) = H.uu;
    }
}

// ---------------------------------------------------------------------------
// GEMM via mma.sync (HMMA): per CTA: 128 rows x 128 cols, K=256.
// Grid: (m_tiles=64, n_split=2, C=32). 256 threads = 8 warps (2m x 4n).
// smem: s_row[128], s_bias[128], A[128][264] fp16, W[128][264] fp16.
// ---------------------------------------------------------------------------
#define RSTR 264                      // fp16 elems per smem row (pad 256->264)
#define RSTRB (RSTR * 2)              // 528 bytes
#define OFF_ROW  0
#define OFF_BIAS 512
#define OFF_A    1024
#define OFF_W    (OFF_A + 128 * RSTRB)        // 1024 + 67584
#define SM_TOTAL (OFF_W + 128 * RSTRB)        // 136192

__device__ __forceinline__ uint32_t smem_u32(const void* p) {
    uint32_t a;
    asm("{ .reg .u64 t; cvta.to.shared.u64 t, %1; cvt.u32.u64 %0, t; }"
        : "=r"(a) : "l"(p));
    return a;
}

#define LDSM_X4(r0, r1, r2, r3, addr)                                       \
    asm volatile("ldmatrix.sync.aligned.m8n8.x4.shared.b16 "                \
                 "{%0,%1,%2,%3}, [%4];"                                     \
                 : "=r"(r0), "=r"(r1), "=r"(r2), "=r"(r3) : "r"(addr))

#define MMA16816(d0, d1, d2, d3, a0, a1, a2, a3, b0, b1)                    \
    asm volatile("mma.sync.aligned.m16n8k16.row.col.f32.f16.f16.f32 "       \
                 "{%0,%1,%2,%3}, {%4,%5,%6,%7}, {%8,%9}, {%0,%1,%2,%3};"    \
                 : "+f"(d0), "+f"(d1), "+f"(d2), "+f"(d3)                   \
                 : "r"(a0), "r"(a1), "r"(a2), "r"(a3), "r"(b0), "r"(b1))

__global__ __launch_bounds__(256, 1)
void gemm_mma_kernel(const float* __restrict__ x,
                     const float* __restrict__ bias,
                     float* __restrict__ out) {
    extern __shared__ char smem[];
    const int c = blockIdx.z;
    const int cnt = g_count[c];
    const int m0 = blockIdx.x * 128;
    if (m0 >= cnt) return;
    const int rows = min(128, cnt - m0);
    const int base = g_offset[c] + m0;
    const int n0 = blockIdx.y * 128;

    const int tid = threadIdx.x;
    const int wid = tid >> 5;
    const int lane = tid & 31;
    const int wm = wid >> 2;      // 0..1 (64 rows each)
    const int wn = wid & 3;       // 0..3 (32 cols each)

    int* s_row = (int*)(smem + OFF_ROW);
    float* s_bias = (float*)(smem + OFF_BIAS);
    const uint32_t sb = smem_u32(smem);

    if (tid < 128) {
        s_row[tid] = g_perm[base + min(tid, rows - 1)];
        s_bias[tid] = bias[(size_t)(n0 + tid) * C_SZ + c];
    }
    __syncthreads();

    // ---- fill A: gathered x rows, fp32 -> fp16 ----
    {
#pragma unroll
        for (int it = 0; it < 16; it++) {
            int task = tid + it * 256;          // 4096 tasks
            int r = task >> 5, g = task & 31;   // row, 8-elem granule
            const float4* src =
                (const float4*)(x + (size_t)s_row[r] * I_SZ + g * 8);
            float4 v0 = src[0], v1 = src[1];
            union { uint4 u; __half2 h[4]; } P;
            P.h[0] = __float22half2_rn(make_float2(v0.x, v0.y));
            P.h[1] = __float22half2_rn(make_float2(v0.z, v0.w));
            P.h[2] = __float22half2_rn(make_float2(v1.x, v1.y));
            P.h[3] = __float22half2_rn(make_float2(v1.z, v1.w));
            *(uint4*)(smem + OFF_A + r * RSTRB + g * 16) = P.u;
        }
    }
    // ---- fill W: fp16 [c][n][k] -> smem ----
    {
        const __half* wc = g_wq + ((size_t)c << 16) + (size_t)n0 * I_SZ;
#pragma unroll
        for (int it = 0; it < 16; it++) {
            int task = tid + it * 256;
            int r = task >> 5, g = task & 31;
            uint4 v = *(const uint4*)(wc + (size_t)r * I_SZ + g * 8);
            *(uint4*)(smem + OFF_W + r * RSTRB + g * 16) = v;
        }
    }
    __syncthreads();

    // ---- main loop ----
    float acc[4][4][4];
#pragma unroll
    for (int i = 0; i < 4; i++)
#pragma unroll
        for (int j = 0; j < 4; j++)
#pragma unroll
            for (int q = 0; q < 4; q++) acc[i][j][q] = 0.0f;

    // A ldmatrix address (per mt): row = wm*64 + mt*16 + (lane&15),
    //                              colbyte = (lane>>4)*16 + k*2
    uint32_t a_addr[4];
#pragma unroll
    for (int mt = 0; mt < 4; mt++)
        a_addr[mt] = sb + OFF_A + (wm * 64 + mt * 16 + (lane & 15)) * RSTRB +
                     (lane >> 4) * 16;
    // B ldmatrix address (per nt-pair p): n = wn*32 + p*16 + (lane>>4)*8 + (lane&7),
    //                                     colbyte = ((lane>>3)&1)*16 + k*2
    uint32_t b_addr[2];
#pragma unroll
    for (int p = 0; p < 2; p++)
        b_addr[p] = sb + OFF_W +
                    (wn * 32 + p * 16 + (lane >> 4) * 8 + (lane & 7)) * RSTRB +
                    ((lane >> 3) & 1) * 16;

#pragma unroll
    for (int ks = 0; ks < 16; ks++) {
        const uint32_t kb = ks * 32;   // 16 fp16 = 32 bytes
        uint32_t a[4][4], b[2][4];
#pragma unroll
        for (int mt = 0; mt < 4; mt++)
            LDSM_X4(a[mt][0], a[mt][1], a[mt][2], a[mt][3], a_addr[mt] + kb);
#pragma unroll
        for (int p = 0; p < 2; p++)
            LDSM_X4(b[p][0], b[p][1], b[p][2], b[p][3], b_addr[p] + kb);
#pragma unroll
        for (int mt = 0; mt < 4; mt++) {
#pragma unroll
            for (int nt = 0; nt < 4; nt++) {
                uint32_t b0 = b[nt >> 1][(nt & 1) * 2 + 0];
                uint32_t b1 = b[nt >> 1][(nt & 1) * 2 + 1];
                MMA16816(acc[mt][nt][0], acc[mt][nt][1],
                         acc[mt][nt][2], acc[mt][nt][3],
                         a[mt][0], a[mt][1], a[mt][2], a[mt][3], b0, b1);
            }
        }
    }

    // ---- epilogue: bias add + scatter (float2 stores) ----
    const int g = lane >> 2, t = lane & 3;
#pragma unroll
    for (int mt = 0; mt < 4; mt++) {
        int rl = wm * 64 + mt * 16 + g;
#pragma unroll
        for (int h = 0; h < 2; h++) {     // row halves: g, g+8
            int rr = rl + h * 8;
            if (rr < rows) {
                float* op = out + (size_t)s_row[rr] * O_SZ + n0;
#pragma unroll
                for (int nt = 0; nt < 4; nt++) {
                    int cl = wn * 32 + nt * 8 + 2 * t;
                    float2 v;
                    v.x = acc[mt][nt][h * 2 + 0] + s_bias[cl + 0];
                    v.y = acc[mt][nt][h * 2 + 1] + s_bias[cl + 1];
                    *(float2*)(op + cl) = v;
                }
            }
        }
    }
}

// ---------------------------------------------------------------------------
// launch
// Inputs: x [B,I] f32, idx [B] i64/i32, weight [O,I,C] f32, bias [O,C] f32
// ---------------------------------------------------------------------------
extern "C" void kernel_launch(void* const* d_in, const int* in_sizes, int n_in,
                              void* d_out, int out_size) {
    const float* x      = (const float*)d_in[0];
    const void*  idx    = d_in[1];
    const float* weight = (const float*)d_in[2];
    const float* bias   = (const float*)d_in[3];
    float* out = (float*)d_out;

    cudaFuncSetAttribute(gemm_mma_kernel,
                         cudaFuncAttributeMaxDynamicSharedMemorySize, SM_TOTAL);

    prep_kernel<<<1, 1024>>>(idx);
    conv_w_kernel<<<O_SZ, 256>>>(weight);
    dim3 grid(B_SZ / 128, O_SZ / 128, C_SZ);
    gemm_mma_kernel<<<grid, 256, SM_TOTAL>>>(x, bias, out);
}

// round 4
// speedup vs baseline: 2.0266x; 1.0977x over previous
#include <cuda_runtime.h>
#include <cuda_fp16.h>
#include <cstdint>

#define B_SZ 8192
#define I_SZ 256
#define O_SZ 256
#define C_SZ 32
#define FULLMASK 0xFFFFFFFFu
#define MAX_TILES 96

// ---------------- scratch (device globals; allocation-free) ----------------
__device__ int g_perm[B_SZ];
__device__ int g_count[C_SZ];
__device__ int g_offset[C_SZ];
__device__ int g_tiles[MAX_TILES];   // packed: c | (mtile<<8) | (rows<<16)
__device__ int g_ntiles;
__device__ __half g_wq[C_SZ * O_SZ * I_SZ];  // [c][o][i] fp16, 4 MB

// ---------------------------------------------------------------------------
// prep: ONE block, 1024 threads, fully atomic-free.
//  - dtype detect (int32 vs int64) over first 8192 words (safe both ways)
//  - warp-private histograms -> cross-warp prefix -> atomic-free scatter
//  - emits packed tile worklist for the GEMM
// ---------------------------------------------------------------------------
__global__ __launch_bounds__(1024, 1)
void prep_kernel(const void* __restrict__ idx_ptr) {
    __shared__ int s_h[32][32];     // [warp][channel]: hist, then cursors
    __shared__ int s_off[32];
    __shared__ int s_cnt[32];
    __shared__ int s_vote[32];
    __shared__ int s_is64;

    const int tid = threadIdx.x;
    const int w = tid >> 5;
    const int lane = tid & 31;

    // ---- detect: 8192 int32 words = 2048 int4, 2 per thread ----
    {
        const int4* p = (const int4*)idx_ptr;
        int4 v0 = p[tid];
        int4 v1 = p[tid + 1024];
        int ok = 1;
        if (v0.y | v0.w | v1.y | v1.w) ok = 0;
        if ((unsigned)v0.x >= 32u || (unsigned)v0.z >= 32u ||
            (unsigned)v1.x >= 32u || (unsigned)v1.z >= 32u) ok = 0;
        int allok = __all_sync(FULLMASK, ok);
        if (lane == 0) s_vote[w] = allok;
    }
    s_h[w][lane] = 0;
    __syncthreads();
    if (tid == 0) {
        int a = 1;
#pragma unroll
        for (int i = 0; i < 32; i++) a &= s_vote[i];
        s_is64 = a;
    }
    __syncthreads();
    const int is64 = s_is64;

    // ---- hist: warp w owns elements w*256 + k*32 + lane ----
    int myc[8];
#pragma unroll
    for (int k = 0; k < 8; k++) {
        int e = w * 256 + k * 32 + lane;
        int c = is64 ? (int)((const long long*)idx_ptr)[e]
                     : ((const int*)idx_ptr)[e];
        myc[k] = c;
        unsigned mask = __match_any_sync(FULLMASK, c);
        if (lane == (__ffs(mask) - 1)) s_h[w][c] += __popc(mask);  // warp-private
    }
    __syncthreads();

    // ---- totals + exclusive prefix over channels (32 threads) ----
    if (tid < 32) {
        const int c = tid;
        int tot = 0;
#pragma unroll
        for (int w2 = 0; w2 < 32; w2++) tot += s_h[w2][c];
        int v = tot;
#pragma unroll
        for (int d = 1; d < 32; d <<= 1) {
            int u = __shfl_up_sync(FULLMASK, v, d);
            if (lane >= d) v += u;
        }
        int off = v - tot;
        s_off[c] = off;
        s_cnt[c] = tot;
        g_offset[c] = off;
        g_count[c] = tot;
        // per-warp exclusive cursors (repurpose s_h)
        int run = off;
#pragma unroll
        for (int w2 = 0; w2 < 32; w2++) {
            int h = s_h[w2][c];
            s_h[w2][c] = run;
            run += h;
        }
    }
    __syncthreads();

    // ---- tile worklist (thread 0, tiny) ----
    if (tid == 0) {
        int nt = 0;
        for (int c = 0; c < 32; c++) {
            int cnt = s_cnt[c];
            for (int m = 0; m * 128 < cnt; m++) {
                int rows = min(128, cnt - m * 128);
                g_tiles[nt++] = c | (m << 8) | (rows << 16);
            }
        }
        g_ntiles = nt;
    }

    // ---- scatter: atomic-free via warp-private cursors ----
#pragma unroll
    for (int k = 0; k < 8; k++) {
        int e = w * 256 + k * 32 + lane;
        int c = myc[k];
        unsigned mask = __match_any_sync(FULLMASK, c);
        int leader = __ffs(mask) - 1;
        int r = __popc(mask & ((1u << lane) - 1u));
        int base = s_h[w][c];
        g_perm[base + r] = e;
        __syncwarp();
        if (lane == leader) s_h[w][c] = base + __popc(mask);
        __syncwarp();
    }
}

// ---------------------------------------------------------------------------
// conv_w: weight [O][I][C] fp32 -> g_wq [C][O][I] fp16 (transpose + convert)
// ---------------------------------------------------------------------------
__global__ void conv_w_kernel(const float* __restrict__ weight) {
    __shared__ float s[I_SZ * 33];
    const int o = blockIdx.x;
    const float* src = weight + (size_t)o * (I_SZ * C_SZ);

    for (int l = threadIdx.x; l < I_SZ * C_SZ; l += blockDim.x) {
        int i = l >> 5, c = l & 31;
        s[i * 33 + c] = src[l];
    }
    __syncthreads();

    for (int u = threadIdx.x; u < (I_SZ * C_SZ) / 4; u += blockDim.x) {
        int c = u >> 6, i4 = u & 63;
        union { uint2 uu; __half h[4]; } H;
#pragma unroll
        for (int j = 0; j < 4; j++)
            H.h[j] = __float2half_rn(s[(i4 * 4 + j) * 33 + c]);
        size_t off = ((size_t)c << 16) + ((size_t)o << 8) + (size_t)i4 * 4;
        *(uint2*)(g_wq + off) = H.uu;
    }
}

// ---------------------------------------------------------------------------
// GEMM via mma.sync (HMMA): per CTA: 128 rows x 128 cols, K=256.
// Grid: (MAX_TILES-1=95, 2). Worklist-scheduled; empty slots exit instantly.
// ---------------------------------------------------------------------------
#define RSTR 264
#define RSTRB (RSTR * 2)
#define OFF_ROW  0
#define OFF_BIAS 512
#define OFF_A    1024
#define OFF_W    (OFF_A + 128 * RSTRB)
#define SM_TOTAL (OFF_W + 128 * RSTRB)   // 136192

__device__ __forceinline__ uint32_t smem_u32(const void* p) {
    uint32_t a;
    asm("{ .reg .u64 t; cvta.to.shared.u64 t, %1; cvt.u32.u64 %0, t; }"
        : "=r"(a) : "l"(p));
    return a;
}

#define LDSM_X4(r0, r1, r2, r3, addr)                                       \
    asm volatile("ldmatrix.sync.aligned.m8n8.x4.shared.b16 "                \
                 "{%0,%1,%2,%3}, [%4];"                                     \
                 : "=r"(r0), "=r"(r1), "=r"(r2), "=r"(r3) : "r"(addr))

#define MMA16816(d0, d1, d2, d3, a0, a1, a2, a3, b0, b1)                    \
    asm volatile("mma.sync.aligned.m16n8k16.row.col.f32.f16.f16.f32 "       \
                 "{%0,%1,%2,%3}, {%4,%5,%6,%7}, {%8,%9}, {%0,%1,%2,%3};"    \
                 : "+f"(d0), "+f"(d1), "+f"(d2), "+f"(d3)                   \
                 : "r"(a0), "r"(a1), "r"(a2), "r"(a3), "r"(b0), "r"(b1))

__global__ __launch_bounds__(256, 1)
void gemm_mma_kernel(const float* __restrict__ x,
                     const float* __restrict__ bias,
                     float* __restrict__ out) {
    extern __shared__ char smem[];
    if ((int)blockIdx.x >= g_ntiles) return;
    const int t = g_tiles[blockIdx.x];
    const int c = t & 31;
    const int m0 = ((t >> 8) & 0xFF) * 128;
    const int rows = (t >> 16) & 0xFF;
    const int base = g_offset[c] + m0;
    const int n0 = blockIdx.y * 128;

    const int tid = threadIdx.x;
    const int wid = tid >> 5;
    const int lane = tid & 31;
    const int wm = wid >> 2;
    const int wn = wid & 3;

    int* s_row = (int*)(smem + OFF_ROW);
    float* s_bias = (float*)(smem + OFF_BIAS);
    const uint32_t sb = smem_u32(smem);

    if (tid < 128) {
        s_row[tid] = g_perm[base + min(tid, rows - 1)];
        s_bias[tid] = bias[(size_t)(n0 + tid) * C_SZ + c];
    }
    __syncthreads();

    // ---- fill A: gathered x rows, fp32 -> fp16 ----
#pragma unroll
    for (int it = 0; it < 16; it++) {
        int task = tid + it * 256;
        int r = task >> 5, g = task & 31;
        const float4* src = (const float4*)(x + (size_t)s_row[r] * I_SZ + g * 8);
        float4 v0 = src[0], v1 = src[1];
        union { uint4 u; __half2 h[4]; } P;
        P.h[0] = __float22half2_rn(make_float2(v0.x, v0.y));
        P.h[1] = __float22half2_rn(make_float2(v0.z, v0.w));
        P.h[2] = __float22half2_rn(make_float2(v1.x, v1.y));
        P.h[3] = __float22half2_rn(make_float2(v1.z, v1.w));
        *(uint4*)(smem + OFF_A + r * RSTRB + g * 16) = P.u;
    }
    // ---- fill W ----
    {
        const __half* wc = g_wq + ((size_t)c << 16) + (size_t)n0 * I_SZ;
#pragma unroll
        for (int it = 0; it < 16; it++) {
            int task = tid + it * 256;
            int r = task >> 5, g = task & 31;
            uint4 v = *(const uint4*)(wc + (size_t)r * I_SZ + g * 8);
            *(uint4*)(smem + OFF_W + r * RSTRB + g * 16) = v;
        }
    }
    __syncthreads();

    float acc[4][4][4];
#pragma unroll
    for (int i = 0; i < 4; i++)
#pragma unroll
        for (int j = 0; j < 4; j++)
#pragma unroll
            for (int q = 0; q < 4; q++) acc[i][j][q] = 0.0f;

    uint32_t a_addr[4];
#pragma unroll
    for (int mt = 0; mt < 4; mt++)
        a_addr[mt] = sb + OFF_A + (wm * 64 + mt * 16 + (lane & 15)) * RSTRB +
                     (lane >> 4) * 16;
    uint32_t b_addr[2];
#pragma unroll
    for (int p = 0; p < 2; p++)
        b_addr[p] = sb + OFF_W +
                    (wn * 32 + p * 16 + (lane >> 4) * 8 + (lane & 7)) * RSTRB +
                    ((lane >> 3) & 1) * 16;

#pragma unroll
    for (int ks = 0; ks < 16; ks++) {
        const uint32_t kb = ks * 32;
        uint32_t a[4][4], b[2][4];
#pragma unroll
        for (int mt = 0; mt < 4; mt++)
            LDSM_X4(a[mt][0], a[mt][1], a[mt][2], a[mt][3], a_addr[mt] + kb);
#pragma unroll
        for (int p = 0; p < 2; p++)
            LDSM_X4(b[p][0], b[p][1], b[p][2], b[p][3], b_addr[p] + kb);
#pragma unroll
        for (int mt = 0; mt < 4; mt++) {
#pragma unroll
            for (int nt = 0; nt < 4; nt++) {
                uint32_t b0 = b[nt >> 1][(nt & 1) * 2 + 0];
                uint32_t b1 = b[nt >> 1][(nt & 1) * 2 + 1];
                MMA16816(acc[mt][nt][0], acc[mt][nt][1],
                         acc[mt][nt][2], acc[mt][nt][3],
                         a[mt][0], a[mt][1], a[mt][2], a[mt][3], b0, b1);
            }
        }
    }

    // ---- epilogue ----
    const int g = lane >> 2, tq = lane & 3;
#pragma unroll
    for (int mt = 0; mt < 4; mt++) {
        int rl = wm * 64 + mt * 16 + g;
#pragma unroll
        for (int h = 0; h < 2; h++) {
            int rr = rl + h * 8;
            if (rr < rows) {
                float* op = out + (size_t)s_row[rr] * O_SZ + n0;
#pragma unroll
                for (int nt = 0; nt < 4; nt++) {
                    int cl = wn * 32 + nt * 8 + 2 * tq;
                    float2 v;
                    v.x = acc[mt][nt][h * 2 + 0] + s_bias[cl + 0];
                    v.y = acc[mt][nt][h * 2 + 1] + s_bias[cl + 1];
                    *(float2*)(op + cl) = v;
                }
            }
        }
    }
}

// ---------------------------------------------------------------------------
// launch
// ---------------------------------------------------------------------------
extern "C" void kernel_launch(void* const* d_in, const int* in_sizes, int n_in,
                              void* d_out, int out_size) {
    const float* x      = (const float*)d_in[0];
    const void*  idx    = d_in[1];
    const float* weight = (const float*)d_in[2];
    const float* bias   = (const float*)d_in[3];
    float* out = (float*)d_out;

    cudaFuncSetAttribute(gemm_mma_kernel,
                         cudaFuncAttributeMaxDynamicSharedMemorySize, SM_TOTAL);

    prep_kernel<<<1, 1024>>>(idx);
    conv_w_kernel<<<O_SZ, 256>>>(weight);
    dim3 grid(MAX_TILES - 1, 2);   // 95 worklist slots x 2 n-halves
    gemm_mma_kernel<<<grid, 256, SM_TOTAL>>>(x, bias, out);
}

// round 5
// speedup vs baseline: 2.0381x; 1.0057x over previous
#include <cuda_runtime.h>
#include <cuda_fp16.h>
#include <cstdint>

#define B_SZ 8192
#define I_SZ 256
#define O_SZ 256
#define C_SZ 32
#define FULLMASK 0xFFFFFFFFu
#define MAX_TILES 96

// ---------------- scratch (device globals; allocation-free) ----------------
__device__ int g_perm[B_SZ];
__device__ int g_offset[C_SZ];
__device__ int g_tiles[MAX_TILES];   // packed: c | (mtile<<8) | (rows<<16)
__device__ int g_ntiles;
__device__ int g_is64;
__device__ int g_ok64[32];
__device__ int g_h64[32 * 8 * 32];   // [block][warp][channel]
__device__ int g_h32[32 * 8 * 32];
__device__ int g_wcur[256 * 32];     // per-warp exclusive cursors [wq][c]
__device__ __half g_wq[C_SZ * O_SZ * I_SZ];  // [c][o][i] fp16, 4 MB

// ---------------------------------------------------------------------------
// K1: blocks 0..255 -> conv_w (weight [O][I][C] f32 -> [C][O][I] f16)
//     blocks 256..287 -> P1 count (dual-dtype per-warp histograms + vote)
// ---------------------------------------------------------------------------
__global__ __launch_bounds__(256, 1)
void k1_convw_count(const float* __restrict__ weight,
                    const void* __restrict__ idx_ptr) {
    __shared__ float s[I_SZ * 33];
    __shared__ int s_h64[8][32];
    __shared__ int s_h32[8][32];
    __shared__ int s_vote[8];

    const int tid = threadIdx.x;

    if (blockIdx.x < 256) {
        // ---------------- conv_w ----------------
        const int o = blockIdx.x;
        const float* src = weight + (size_t)o * (I_SZ * C_SZ);
        for (int l = tid; l < I_SZ * C_SZ; l += 256) {
            int i = l >> 5, c = l & 31;
            s[i * 33 + c] = src[l];
        }
        __syncthreads();
        for (int u = tid; u < (I_SZ * C_SZ) / 4; u += 256) {
            int c = u >> 6, i4 = u & 63;
            union { uint2 uu; __half h[4]; } H;
#pragma unroll
            for (int j = 0; j < 4; j++)
                H.h[j] = __float2half_rn(s[(i4 * 4 + j) * 33 + c]);
            size_t off = ((size_t)c << 16) + ((size_t)o << 8) + (size_t)i4 * 4;
            *(uint2*)(g_wq + off) = H.uu;
        }
        return;
    }

    // ---------------- P1: count ----------------
    const int b2 = blockIdx.x - 256;
    const int w = tid >> 5;
    const int lane = tid & 31;
    const int e = b2 * 256 + tid;

    if (tid < 256) {
        if (w == 0 && lane < 8) s_vote[lane] = 0;
        s_h64[w][lane] = 0;   // lane<32 always
        s_h32[w][lane] = 0;
    }
    __syncthreads();

    const int v32 = ((const int*)idx_ptr)[e];
    const int2 v64 = ((const int2*)idx_ptr)[e];

    int ok64 = (v64.y == 0) && ((unsigned)v64.x < 32u);
    int allok = __all_sync(FULLMASK, ok64);
    if (lane == 0) s_vote[w] = allok;

    // warp-private hist of both interpretations (values masked for safety)
    {
        int c = v64.x & 31;
        unsigned m = __match_any_sync(FULLMASK, c);
        if (lane == (__ffs(m) - 1)) s_h64[w][c] += __popc(m);
    }
    {
        int c = v32 & 31;
        unsigned m = __match_any_sync(FULLMASK, c);
        if (lane == (__ffs(m) - 1)) s_h32[w][c] += __popc(m);
    }
    __syncthreads();

    if (tid == 0) {
        int a = 1;
#pragma unroll
        for (int i = 0; i < 8; i++) a &= s_vote[i];
        g_ok64[b2] = a;
    }
    // write warp hists: 256 entries each
    g_h64[b2 * 256 + tid] = s_h64[w][lane];
    g_h32[b2 * 256 + tid] = s_h32[w][lane];
}

// ---------------------------------------------------------------------------
// K2: 1 block, 1024 threads. dtype resolve, offsets, per-warp cursors, tiles.
// ---------------------------------------------------------------------------
__global__ __launch_bounds__(1024, 1)
void k2_prefix() {
    __shared__ int s_cur[256 * 32];   // 32 KB
    __shared__ int s_tot[32];
    __shared__ int s_off[32];
    __shared__ int s_is64;

    const int tid = threadIdx.x;
    const int wid = tid >> 5;
    const int lane = tid & 31;

    if (tid < 32) {
        int v = g_ok64[tid];
        v = __all_sync(FULLMASK, v);
        if (tid == 0) { s_is64 = v; g_is64 = v; }
    }
    __syncthreads();
    const int* H = s_is64 ? g_h64 : g_h32;

    // warp 'wid' owns channel c = wid: prefix over 256 warp-hists
    {
        const int c = wid;
        int carry = 0;
#pragma unroll
        for (int r = 0; r < 8; r++) {
            int wq = r * 32 + lane;
            int v = H[wq * 32 + c];
            int incl = v;
#pragma unroll
            for (int d = 1; d < 32; d <<= 1) {
                int u = __shfl_up_sync(FULLMASK, incl, d);
                if (lane >= d) incl += u;
            }
            s_cur[wq * 32 + c] = carry + (incl - v);
            carry += __shfl_sync(FULLMASK, incl, 31);
        }
        if (lane == 0) s_tot[c] = carry;
    }
    __syncthreads();

    if (tid < 32) {
        int v = s_tot[tid];
        int incl = v;
#pragma unroll
        for (int d = 1; d < 32; d <<= 1) {
            int u = __shfl_up_sync(FULLMASK, incl, d);
            if (lane >= d) incl += u;
        }
        int off = incl - v;
        s_off[tid] = off;
        g_offset[tid] = off;
    }
    __syncthreads();

    if (tid == 0) {
        int nt = 0;
        for (int c = 0; c < 32; c++) {
            int cnt = s_tot[c];
            for (int m = 0; m * 128 < cnt; m++) {
                int rows = min(128, cnt - m * 128);
                g_tiles[nt++] = c | (m << 8) | (rows << 16);
            }
        }
        g_ntiles = nt;
    }

    // cursors += channel base
#pragma unroll
    for (int i = 0; i < 8; i++) {
        int idx = tid + i * 1024;
        g_wcur[idx] = s_cur[idx] + s_off[idx & 31];
    }
}

// ---------------------------------------------------------------------------
// K3: 32 blocks x 256 threads. Atomic-free scatter via per-warp cursors.
// ---------------------------------------------------------------------------
__global__ __launch_bounds__(256, 1)
void k3_scatter(const void* __restrict__ idx_ptr) {
    const int tid = threadIdx.x;
    const int w = tid >> 5;
    const int lane = tid & 31;
    const int b = blockIdx.x;
    const int e = b * 256 + tid;
    const int is64 = g_is64;

    int c = is64 ? (((const int2*)idx_ptr)[e].x & 31)
                 : (((const int*)idx_ptr)[e] & 31);
    unsigned m = __match_any_sync(FULLMASK, c);
    int rank = __popc(m & ((1u << lane) - 1u));
    int base = g_wcur[(b * 8 + w) * 32 + c];
    g_perm[base + rank] = e;
}

// ---------------------------------------------------------------------------
// GEMM via mma.sync (HMMA): per CTA: 128 rows x 128 cols, K=256.
// Grid: (96, 2). Worklist-scheduled; empty slots exit instantly.
// ---------------------------------------------------------------------------
#define RSTR 264
#define RSTRB (RSTR * 2)
#define OFF_ROW  0
#define OFF_BIAS 512
#define OFF_A    1024
#define OFF_W    (OFF_A + 128 * RSTRB)
#define SM_TOTAL (OFF_W + 128 * RSTRB)   // 136192

__device__ __forceinline__ uint32_t smem_u32(const void* p) {
    uint32_t a;
    asm("{ .reg .u64 t; cvta.to.shared.u64 t, %1; cvt.u32.u64 %0, t; }"
        : "=r"(a) : "l"(p));
    return a;
}

#define LDSM_X4(r0, r1, r2, r3, addr)                                       \
    asm volatile("ldmatrix.sync.aligned.m8n8.x4.shared.b16 "                \
                 "{%0,%1,%2,%3}, [%4];"                                     \
                 : "=r"(r0), "=r"(r1), "=r"(r2), "=r"(r3) : "r"(addr))

#define MMA16816(d0, d1, d2, d3, a0, a1, a2, a3, b0, b1)                    \
    asm volatile("mma.sync.aligned.m16n8k16.row.col.f32.f16.f16.f32 "       \
                 "{%0,%1,%2,%3}, {%4,%5,%6,%7}, {%8,%9}, {%0,%1,%2,%3};"    \
                 : "+f"(d0), "+f"(d1), "+f"(d2), "+f"(d3)                   \
                 : "r"(a0), "r"(a1), "r"(a2), "r"(a3), "r"(b0), "r"(b1))

__global__ __launch_bounds__(256, 1)
void gemm_mma_kernel(const float* __restrict__ x,
                     const float* __restrict__ bias,
                     float* __restrict__ out) {
    extern __shared__ char smem[];
    if ((int)blockIdx.x >= g_ntiles) return;
    const int t = g_tiles[blockIdx.x];
    const int c = t & 31;
    const int m0 = ((t >> 8) & 0xFF) * 128;
    const int rows = (t >> 16) & 0xFF;
    const int base = g_offset[c] + m0;
    const int n0 = blockIdx.y * 128;

    const int tid = threadIdx.x;
    const int wid = tid >> 5;
    const int lane = tid & 31;
    const int wm = wid >> 2;
    const int wn = wid & 3;

    int* s_row = (int*)(smem + OFF_ROW);
    float* s_bias = (float*)(smem + OFF_BIAS);
    const uint32_t sb = smem_u32(smem);

    if (tid < 128) {
        s_row[tid] = g_perm[base + min(tid, rows - 1)];
        s_bias[tid] = bias[(size_t)(n0 + tid) * C_SZ + c];
    }
    __syncthreads();

    // ---- fill A: gathered x rows, fp32 -> fp16 ----
#pragma unroll
    for (int it = 0; it < 16; it++) {
        int task = tid + it * 256;
        int r = task >> 5, g = task & 31;
        const float4* src = (const float4*)(x + (size_t)s_row[r] * I_SZ + g * 8);
        float4 v0 = src[0], v1 = src[1];
        union { uint4 u; __half2 h[4]; } P;
        P.h[0] = __float22half2_rn(make_float2(v0.x, v0.y));
        P.h[1] = __float22half2_rn(make_float2(v0.z, v0.w));
        P.h[2] = __float22half2_rn(make_float2(v1.x, v1.y));
        P.h[3] = __float22half2_rn(make_float2(v1.z, v1.w));
        *(uint4*)(smem + OFF_A + r * RSTRB + g * 16) = P.u;
    }
    // ---- fill W ----
    {
        const __half* wc = g_wq + ((size_t)c << 16) + (size_t)n0 * I_SZ;
#pragma unroll
        for (int it = 0; it < 16; it++) {
            int task = tid + it * 256;
            int r = task >> 5, g = task & 31;
            uint4 v = *(const uint4*)(wc + (size_t)r * I_SZ + g * 8);
            *(uint4*)(smem + OFF_W + r * RSTRB + g * 16) = v;
        }
    }
    __syncthreads();

    float acc[4][4][4];
#pragma unroll
    for (int i = 0; i < 4; i++)
#pragma unroll
        for (int j = 0; j < 4; j++)
#pragma unroll
            for (int q = 0; q < 4; q++) acc[i][j][q] = 0.0f;

    uint32_t a_addr[4];
#pragma unroll
    for (int mt = 0; mt < 4; mt++)
        a_addr[mt] = sb + OFF_A + (wm * 64 + mt * 16 + (lane & 15)) * RSTRB +
                     (lane >> 4) * 16;
    uint32_t b_addr[2];
#pragma unroll
    for (int p = 0; p < 2; p++)
        b_addr[p] = sb + OFF_W +
                    (wn * 32 + p * 16 + (lane >> 4) * 8 + (lane & 7)) * RSTRB +
                    ((lane >> 3) & 1) * 16;

#pragma unroll
    for (int ks = 0; ks < 16; ks++) {
        const uint32_t kb = ks * 32;
        uint32_t a[4][4], b[2][4];
#pragma unroll
        for (int mt = 0; mt < 4; mt++)
            LDSM_X4(a[mt][0], a[mt][1], a[mt][2], a[mt][3], a_addr[mt] + kb);
#pragma unroll
        for (int p = 0; p < 2; p++)
            LDSM_X4(b[p][0], b[p][1], b[p][2], b[p][3], b_addr[p] + kb);
#pragma unroll
        for (int mt = 0; mt < 4; mt++) {
#pragma unroll
            for (int nt = 0; nt < 4; nt++) {
                uint32_t b0 = b[nt >> 1][(nt & 1) * 2 + 0];
                uint32_t b1 = b[nt >> 1][(nt & 1) * 2 + 1];
                MMA16816(acc[mt][nt][0], acc[mt][nt][1],
                         acc[mt][nt][2], acc[mt][nt][3],
                         a[mt][0], a[mt][1], a[mt][2], a[mt][3], b0, b1);
            }
        }
    }

    // ---- epilogue ----
    const int g = lane >> 2, tq = lane & 3;
#pragma unroll
    for (int mt = 0; mt < 4; mt++) {
        int rl = wm * 64 + mt * 16 + g;
#pragma unroll
        for (int h = 0; h < 2; h++) {
            int rr = rl + h * 8;
            if (rr < rows) {
                float* op = out + (size_t)s_row[rr] * O_SZ + n0;
#pragma unroll
                for (int nt = 0; nt < 4; nt++) {
                    int cl = wn * 32 + nt * 8 + 2 * tq;
                    float2 v;
                    v.x = acc[mt][nt][h * 2 + 0] + s_bias[cl + 0];
                    v.y = acc[mt][nt][h * 2 + 1] + s_bias[cl + 1];
                    *(float2*)(op + cl) = v;
                }
            }
        }
    }
}

// ---------------------------------------------------------------------------
// launch
// ---------------------------------------------------------------------------
extern "C" void kernel_launch(void* const* d_in, const int* in_sizes, int n_in,
                              void* d_out, int out_size) {
    const float* x      = (const float*)d_in[0];
    const void*  idx    = d_in[1];
    const float* weight = (const float*)d_in[2];
    const float* bias   = (const float*)d_in[3];
    float* out = (float*)d_out;

    cudaFuncSetAttribute(gemm_mma_kernel,
                         cudaFuncAttributeMaxDynamicSharedMemorySize, SM_TOTAL);

    k1_convw_count<<<288, 256>>>(weight, idx);
    k2_prefix<<<1, 1024>>>();
    k3_scatter<<<32, 256>>>(idx);
    dim3 grid(MAX_TILES, 2);
    gemm_mma_kernel<<<grid, 256, SM_TOTAL>>>(x, bias, out);
}